// round 8
// baseline (speedup 1.0000x reference)
#include <cuda_runtime.h>
#include <cuda_bf16.h>
#include <cstdint>

// out = relu(x @ W_w^T + W_b)   (attention collapses: softmax rows sum to 1).
//
// R8 = R5 skeleton (smem staging, 8 warps, 2 CTA/SM, reg-prefetch pipeline,
// 1 barrier/chunk) with warp tile 32x64 in a 128x128 CTA:
//   LDSM bytes/MMA 170 -> 128 (fragment duplication 4x2 -> balanced),
//   per-warp MMA chain doubles (96/chunk, 64 accumulators).
// B-fragment jp-blocking keeps live regs ~128.

#define D_DIM 256
#define BM 128
#define BN 128
#define BK 32
#define N_CHUNKS (D_DIM / BK)          // 8
#define ROWB 80                        // (32+8) bf16 row stride: conflict-free ldsm

#define T_BYTES (BM * ROWB)            // 10240 (one hi or lo tile, 128 rows)
#define OFF_AH 0
#define OFF_AL (OFF_AH + T_BYTES)
#define OFF_BH (OFF_AL + T_BYTES)
#define OFF_BL (OFF_BH + T_BYTES)
#define STAGE_BYTES (OFF_BL + T_BYTES) // 40960
#define SMEM_TOTAL (2 * STAGE_BYTES)   // 81920

__device__ __forceinline__ uint32_t smem_u32(const void* p) {
    uint32_t a;
    asm("{ .reg .u64 t; cvta.to.shared.u64 t, %1; cvt.u32.u64 %0, t; }" : "=r"(a) : "l"(p));
    return a;
}

__device__ __forceinline__ void ldsm_x4(uint32_t* r, uint32_t addr) {
    asm volatile("ldmatrix.sync.aligned.m8n8.x4.shared.b16 {%0,%1,%2,%3}, [%4];"
                 : "=r"(r[0]), "=r"(r[1]), "=r"(r[2]), "=r"(r[3]) : "r"(addr));
}

__device__ __forceinline__ void mma_bf16(float* d, const uint32_t* a, const uint32_t* b) {
    asm volatile("mma.sync.aligned.m16n8k16.row.col.f32.bf16.bf16.f32 "
                 "{%0,%1,%2,%3}, {%4,%5,%6,%7}, {%8,%9}, {%0,%1,%2,%3};"
                 : "+f"(d[0]), "+f"(d[1]), "+f"(d[2]), "+f"(d[3])
                 : "r"(a[0]), "r"(a[1]), "r"(a[2]), "r"(a[3]),
                   "r"(b[0]), "r"(b[1]));
}

// Split a float4 into bf16 hi + bf16 residual lo, store 8 B each.
__device__ __forceinline__ void split_store(uint32_t hi_addr, uint32_t lo_addr, float4 v) {
    __nv_bfloat162 h0 = __floats2bfloat162_rn(v.x, v.y);
    __nv_bfloat162 h1 = __floats2bfloat162_rn(v.z, v.w);
    float2 f0 = __bfloat1622float2(h0);
    float2 f1 = __bfloat1622float2(h1);
    __nv_bfloat162 l0 = __floats2bfloat162_rn(v.x - f0.x, v.y - f0.y);
    __nv_bfloat162 l1 = __floats2bfloat162_rn(v.z - f1.x, v.w - f1.y);
    uint32_t h0u = *(uint32_t*)&h0, h1u = *(uint32_t*)&h1;
    uint32_t l0u = *(uint32_t*)&l0, l1u = *(uint32_t*)&l1;
    asm volatile("st.shared.v2.b32 [%0], {%1, %2};" :: "r"(hi_addr), "r"(h0u), "r"(h1u) : "memory");
    asm volatile("st.shared.v2.b32 [%0], {%1, %2};" :: "r"(lo_addr), "r"(l0u), "r"(l1u) : "memory");
}

__global__ __launch_bounds__(256, 2)
void fcgat_hmma(const float* __restrict__ A,     // x  [32768, 256]
                const float* __restrict__ W,     // W  [256, 256]
                const float* __restrict__ bias,  // [256]
                float* __restrict__ C)           // [32768, 256]
{
    extern __shared__ __align__(16) unsigned char smem[];
    const uint32_t sb = smem_u32(smem);

    const int t   = threadIdx.x;
    const int l   = t & 31;
    const int wid = t >> 5;
    const int wm  = wid & 3;          // 4 warps along M (32 rows each)
    const int wn  = wid >> 2;         // 2 warps along N (64 cols each)
    const int m0  = wm * 32;
    const int n0  = wn * 64;

    const float* Ag = A + (size_t)blockIdx.y * BM * D_DIM;
    const float* Bg = W + (size_t)blockIdx.x * BN * D_DIM;

    float acc[2][8][4];
    #pragma unroll
    for (int i = 0; i < 2; i++)
        #pragma unroll
        for (int j = 0; j < 8; j++)
            #pragma unroll
            for (int c = 0; c < 4; c++)
                acc[i][j][c] = 0.0f;

    const uint32_t a_lane = (uint32_t)((m0 + (l & 15)) * ROWB + (l >> 4) * 16);
    const uint32_t b_lane = (uint32_t)((n0 + (l & 7) + ((l >> 4) << 3)) * ROWB
                                       + ((l >> 3) & 1) * 16);

    float4 pa[4], pb[4];

    // ---- prologue: load + store chunk 0 ----
    // A and B each: 128 rows x 8 float4 = 1024 -> 4/thread.
    #pragma unroll
    for (int i = 0; i < 4; i++) {
        int idx = t + i * 256;
        pa[i] = *(const float4*)(Ag + (size_t)(idx >> 3) * D_DIM + (idx & 7) * 4);
        pb[i] = *(const float4*)(Bg + (size_t)(idx >> 3) * D_DIM + (idx & 7) * 4);
    }
    #pragma unroll
    for (int i = 0; i < 4; i++) {
        int idx = t + i * 256;
        uint32_t so = (uint32_t)((idx >> 3) * ROWB + (idx & 7) * 8);
        split_store(sb + OFF_AH + so, sb + OFF_AL + so, pa[i]);
        split_store(sb + OFF_BH + so, sb + OFF_BL + so, pb[i]);
    }
    __syncthreads();

    uint32_t stage = 0;
    for (int ch = 0; ch < N_CHUNKS; ch++) {
        const bool more = (ch + 1 < N_CHUNKS);
        const int kn = (ch + 1) * BK;

        // (1) prefetch next chunk (latency hidden behind 192 MMAs below)
        if (more) {
            #pragma unroll
            for (int i = 0; i < 4; i++) {
                int idx = t + i * 256;
                pa[i] = *(const float4*)(Ag + (size_t)(idx >> 3) * D_DIM + kn + (idx & 7) * 4);
                pb[i] = *(const float4*)(Bg + (size_t)(idx >> 3) * D_DIM + kn + (idx & 7) * 4);
            }
        }

        // (2) compute current chunk from stage
        const uint32_t abase = sb + stage;
        #pragma unroll
        for (int ks = 0; ks < 2; ks++) {
            const uint32_t ko = (uint32_t)(ks * 32);   // 16 bf16 = 32 B

            uint32_t ah[2][4], al[2][4];
            #pragma unroll
            for (int i = 0; i < 2; i++) {
                ldsm_x4(ah[i], abase + OFF_AH + a_lane + ko + i * 16 * ROWB);
                ldsm_x4(al[i], abase + OFF_AL + a_lane + ko + i * 16 * ROWB);
            }
            // jp-blocked B: load one 16-col block, consume with 12 MMAs.
            #pragma unroll
            for (int jp = 0; jp < 4; jp++) {
                uint32_t bh[4], bl[4];
                ldsm_x4(bh, abase + OFF_BH + b_lane + ko + jp * 16 * ROWB);
                ldsm_x4(bl, abase + OFF_BL + b_lane + ko + jp * 16 * ROWB);
                #pragma unroll
                for (int i = 0; i < 2; i++)
                    #pragma unroll
                    for (int jj = 0; jj < 2; jj++) {
                        const int j = jp * 2 + jj;
                        const uint32_t* bhf = bh + jj * 2;
                        const uint32_t* blf = bl + jj * 2;
                        mma_bf16(acc[i][j], ah[i], bhf);   // xh * Wh
                        mma_bf16(acc[i][j], ah[i], blf);   // xh * Wl
                        mma_bf16(acc[i][j], al[i], bhf);   // xl * Wh
                    }
            }
        }

        // (3) convert + store next chunk into the other stage
        if (more) {
            const uint32_t nbase = sb + (stage ^ STAGE_BYTES);
            #pragma unroll
            for (int i = 0; i < 4; i++) {
                int idx = t + i * 256;
                uint32_t so = (uint32_t)((idx >> 3) * ROWB + (idx & 7) * 8);
                split_store(nbase + OFF_AH + so, nbase + OFF_AL + so, pa[i]);
                split_store(nbase + OFF_BH + so, nbase + OFF_BL + so, pb[i]);
            }
        }

        // (4) single barrier per chunk
        __syncthreads();
        stage ^= STAGE_BYTES;
    }

    // ---- epilogue: bias + relu ----
    const int g  = l >> 2;
    const int tc = l & 3;
    #pragma unroll
    for (int i = 0; i < 2; i++) {
        const size_t r0 = (size_t)blockIdx.y * BM + m0 + 16 * i + g;
        const size_t r1 = r0 + 8;
        #pragma unroll
        for (int j = 0; j < 8; j++) {
            const int col = blockIdx.x * BN + n0 + 8 * j + 2 * tc;
            float2 bv = *(const float2*)(bias + col);
            float2 o0, o1;
            o0.x = fmaxf(acc[i][j][0] + bv.x, 0.0f);
            o0.y = fmaxf(acc[i][j][1] + bv.y, 0.0f);
            o1.x = fmaxf(acc[i][j][2] + bv.x, 0.0f);
            o1.y = fmaxf(acc[i][j][3] + bv.y, 0.0f);
            *(float2*)(C + r0 * D_DIM + col) = o0;
            *(float2*)(C + r1 * D_DIM + col) = o1;
        }
    }
}

extern "C" void kernel_launch(void* const* d_in, const int* in_sizes, int n_in,
                              void* d_out, int out_size)
{
    const float* x   = (const float*)d_in[0];
    const float* W_w = (const float*)d_in[1];
    const float* W_b = (const float*)d_in[2];
    float* out = (float*)d_out;

    int M = in_sizes[0] / D_DIM;                  // 32768
    cudaFuncSetAttribute(fcgat_hmma,
                         cudaFuncAttributeMaxDynamicSharedMemorySize, SMEM_TOTAL);
    dim3 grid(D_DIM / BN, M / BM);                // (2, 256) = 512 CTAs
    fcgat_hmma<<<grid, 256, SMEM_TOTAL>>>(x, W_w, W_b, out);
}

// round 9
// speedup vs baseline: 1.4023x; 1.4023x over previous
#include <cuda_runtime.h>
#include <cuda_fp16.h>
#include <cstdint>

// out = relu(x @ W_w^T + W_b)   (attention collapses: softmax rows sum to 1).
//
// R9 = R5 skeleton UNCHANGED (8 warps 4x2, warp tile 32x32, BM128/BN64,
// double-buffered smem, reg prefetch, 1 barrier/chunk) with the precision
// plan switched from bf16 3-product to fp16 2-product:
//   x = xh + xl (both fp16, 22 mantissa bits total), W ~= Wh (fp16)
//   x@W ~= xh@Wh + xl@Wh ; dropped x@Wl -> rel_err ~ 2^-11/sqrt(3) ~ 2.8e-4
// Tensor-pipe work: -33% (32 vs 48 MMAs/chunk); B smem/convert halved.

#define D_DIM 256
#define BM 128
#define BN 64
#define BK 32
#define N_CHUNKS (D_DIM / BK)      // 8
#define ROWB 80                    // smem row stride: (32+8) fp16 -> conflict-free ldsm

#define OFF_AH 0
#define OFF_AL (OFF_AH + BM * ROWB)     // 10240
#define OFF_BH (OFF_AL + BM * ROWB)     // 20480
#define STAGE_BYTES (OFF_BH + BN * ROWB) // 25600
#define SMEM_TOTAL (2 * STAGE_BYTES)     // 51200

__device__ __forceinline__ uint32_t smem_u32(const void* p) {
    uint32_t a;
    asm("{ .reg .u64 t; cvta.to.shared.u64 t, %1; cvt.u32.u64 %0, t; }" : "=r"(a) : "l"(p));
    return a;
}

__device__ __forceinline__ void ldsm_x4(uint32_t* r, uint32_t addr) {
    asm volatile("ldmatrix.sync.aligned.m8n8.x4.shared.b16 {%0,%1,%2,%3}, [%4];"
                 : "=r"(r[0]), "=r"(r[1]), "=r"(r[2]), "=r"(r[3]) : "r"(addr));
}

__device__ __forceinline__ void mma_f16(float* d, const uint32_t* a, const uint32_t* b) {
    asm volatile("mma.sync.aligned.m16n8k16.row.col.f32.f16.f16.f32 "
                 "{%0,%1,%2,%3}, {%4,%5,%6,%7}, {%8,%9}, {%0,%1,%2,%3};"
                 : "+f"(d[0]), "+f"(d[1]), "+f"(d[2]), "+f"(d[3])
                 : "r"(a[0]), "r"(a[1]), "r"(a[2]), "r"(a[3]),
                   "r"(b[0]), "r"(b[1]));
}

// Split a float4 into fp16 hi + fp16 residual lo, store 8 B each (A path).
__device__ __forceinline__ void split_store_a(uint32_t hi_addr, uint32_t lo_addr, float4 v) {
    __half2 h0 = __floats2half2_rn(v.x, v.y);
    __half2 h1 = __floats2half2_rn(v.z, v.w);
    float2 f0 = __half22float2(h0);
    float2 f1 = __half22float2(h1);
    __half2 l0 = __floats2half2_rn(v.x - f0.x, v.y - f0.y);
    __half2 l1 = __floats2half2_rn(v.z - f1.x, v.w - f1.y);
    uint32_t h0u = *(uint32_t*)&h0, h1u = *(uint32_t*)&h1;
    uint32_t l0u = *(uint32_t*)&l0, l1u = *(uint32_t*)&l1;
    asm volatile("st.shared.v2.b32 [%0], {%1, %2};" :: "r"(hi_addr), "r"(h0u), "r"(h1u) : "memory");
    asm volatile("st.shared.v2.b32 [%0], {%1, %2};" :: "r"(lo_addr), "r"(l0u), "r"(l1u) : "memory");
}

// B: single fp16 rounding, 8 B store.
__device__ __forceinline__ void cvt_store_b(uint32_t addr, float4 v) {
    __half2 h0 = __floats2half2_rn(v.x, v.y);
    __half2 h1 = __floats2half2_rn(v.z, v.w);
    uint32_t h0u = *(uint32_t*)&h0, h1u = *(uint32_t*)&h1;
    asm volatile("st.shared.v2.b32 [%0], {%1, %2};" :: "r"(addr), "r"(h0u), "r"(h1u) : "memory");
}

__global__ __launch_bounds__(256, 2)
void fcgat_hmma(const float* __restrict__ A,     // x  [32768, 256]
                const float* __restrict__ W,     // W  [256, 256]
                const float* __restrict__ bias,  // [256]
                float* __restrict__ C)           // [32768, 256]
{
    extern __shared__ __align__(16) unsigned char smem[];
    const uint32_t sb = smem_u32(smem);

    const int t   = threadIdx.x;
    const int l   = t & 31;
    const int wid = t >> 5;
    const int wm  = wid & 3;          // 4 warps along M
    const int wn  = wid >> 2;         // 2 warps along N
    const int m0  = wm * 32;
    const int n0  = wn * 32;

    const float* Ag = A + (size_t)blockIdx.y * BM * D_DIM;
    const float* Bg = W + (size_t)blockIdx.x * BN * D_DIM;

    float acc[2][4][4];
    #pragma unroll
    for (int i = 0; i < 2; i++)
        #pragma unroll
        for (int j = 0; j < 4; j++)
            #pragma unroll
            for (int c = 0; c < 4; c++)
                acc[i][j][c] = 0.0f;

    const uint32_t a_lane = (uint32_t)((m0 + (l & 15)) * ROWB + (l >> 4) * 16);
    const uint32_t b_lane = (uint32_t)((n0 + (l & 7) + ((l >> 4) << 3)) * ROWB
                                       + ((l >> 3) & 1) * 16);

    float4 pa[4];
    float4 pb[2];

    // ---- prologue: load + store chunk 0 ----
    #pragma unroll
    for (int i = 0; i < 4; i++) {
        int idx = t + i * 256;
        pa[i] = *(const float4*)(Ag + (size_t)(idx >> 3) * D_DIM + (idx & 7) * 4);
    }
    #pragma unroll
    for (int i = 0; i < 2; i++) {
        int idx = t + i * 256;
        pb[i] = *(const float4*)(Bg + (size_t)(idx >> 3) * D_DIM + (idx & 7) * 4);
    }
    #pragma unroll
    for (int i = 0; i < 4; i++) {
        int idx = t + i * 256;
        uint32_t so = (uint32_t)((idx >> 3) * ROWB + (idx & 7) * 8);
        split_store_a(sb + OFF_AH + so, sb + OFF_AL + so, pa[i]);
    }
    #pragma unroll
    for (int i = 0; i < 2; i++) {
        int idx = t + i * 256;
        uint32_t so = (uint32_t)((idx >> 3) * ROWB + (idx & 7) * 8);
        cvt_store_b(sb + OFF_BH + so, pb[i]);
    }
    __syncthreads();

    uint32_t stage = 0;
    for (int ch = 0; ch < N_CHUNKS; ch++) {
        const bool more = (ch + 1 < N_CHUNKS);
        const int kn = (ch + 1) * BK;

        // (1) issue next chunk's global loads (latency hidden behind MMAs)
        if (more) {
            #pragma unroll
            for (int i = 0; i < 4; i++) {
                int idx = t + i * 256;
                pa[i] = *(const float4*)(Ag + (size_t)(idx >> 3) * D_DIM + kn + (idx & 7) * 4);
            }
            #pragma unroll
            for (int i = 0; i < 2; i++) {
                int idx = t + i * 256;
                pb[i] = *(const float4*)(Bg + (size_t)(idx >> 3) * D_DIM + kn + (idx & 7) * 4);
            }
        }

        // (2) compute current chunk from stage `stage`
        const uint32_t base = sb + stage;
        #pragma unroll
        for (int ks = 0; ks < 2; ks++) {
            const uint32_t ko = (uint32_t)(ks * 32);   // 16 fp16 = 32 B
            uint32_t ah[2][4], al[2][4], bh[2][4];
            #pragma unroll
            for (int i = 0; i < 2; i++) {
                ldsm_x4(ah[i], base + OFF_AH + a_lane + ko + i * 16 * ROWB);
                ldsm_x4(al[i], base + OFF_AL + a_lane + ko + i * 16 * ROWB);
            }
            #pragma unroll
            for (int jp = 0; jp < 2; jp++)
                ldsm_x4(bh[jp], base + OFF_BH + b_lane + ko + jp * 16 * ROWB);

            #pragma unroll
            for (int i = 0; i < 2; i++)
                #pragma unroll
                for (int j = 0; j < 4; j++) {
                    const uint32_t* bhf = bh[j >> 1] + (j & 1) * 2;
                    mma_f16(acc[i][j], ah[i], bhf);   // xh * Wh
                    mma_f16(acc[i][j], al[i], bhf);   // xl * Wh
                }
        }

        // (3) convert + store next chunk into the other stage
        const uint32_t nbase = sb + (stage ^ STAGE_BYTES);
        if (more) {
            #pragma unroll
            for (int i = 0; i < 4; i++) {
                int idx = t + i * 256;
                uint32_t so = (uint32_t)((idx >> 3) * ROWB + (idx & 7) * 8);
                split_store_a(nbase + OFF_AH + so, nbase + OFF_AL + so, pa[i]);
            }
            #pragma unroll
            for (int i = 0; i < 2; i++) {
                int idx = t + i * 256;
                uint32_t so = (uint32_t)((idx >> 3) * ROWB + (idx & 7) * 8);
                cvt_store_b(nbase + OFF_BH + so, pb[i]);
            }
        }

        // (4) single barrier per chunk
        __syncthreads();
        stage ^= STAGE_BYTES;
    }

    // ---- epilogue: bias + relu ----
    const int g  = l >> 2;
    const int tc = l & 3;
    #pragma unroll
    for (int i = 0; i < 2; i++) {
        const size_t r0 = (size_t)blockIdx.y * BM + m0 + 16 * i + g;
        const size_t r1 = r0 + 8;
        #pragma unroll
        for (int j = 0; j < 4; j++) {
            const int col = blockIdx.x * BN + n0 + 8 * j + 2 * tc;
            float2 bv = *(const float2*)(bias + col);
            float2 o0, o1;
            o0.x = fmaxf(acc[i][j][0] + bv.x, 0.0f);
            o0.y = fmaxf(acc[i][j][1] + bv.y, 0.0f);
            o1.x = fmaxf(acc[i][j][2] + bv.x, 0.0f);
            o1.y = fmaxf(acc[i][j][3] + bv.y, 0.0f);
            *(float2*)(C + r0 * D_DIM + col) = o0;
            *(float2*)(C + r1 * D_DIM + col) = o1;
        }
    }
}

extern "C" void kernel_launch(void* const* d_in, const int* in_sizes, int n_in,
                              void* d_out, int out_size)
{
    const float* x   = (const float*)d_in[0];
    const float* W_w = (const float*)d_in[1];
    const float* W_b = (const float*)d_in[2];
    float* out = (float*)d_out;

    int M = in_sizes[0] / D_DIM;                  // 32768
    cudaFuncSetAttribute(fcgat_hmma,
                         cudaFuncAttributeMaxDynamicSharedMemorySize, SMEM_TOTAL);
    dim3 grid(D_DIM / BN, M / BM);                // (4, 256) = 1024 CTAs
    fcgat_hmma<<<grid, 256, SMEM_TOTAL>>>(x, W_w, W_b, out);
}

// round 10
// speedup vs baseline: 1.8043x; 1.2866x over previous
#include <cuda_runtime.h>
#include <cuda_fp16.h>
#include <cstdint>

// out = relu(x @ W_w^T + W_b)   (attention collapses: softmax rows sum to 1).
//
// R10 = R9 skeleton with the xl (A residual) path deleted: plain fp16 x fp16
// single-product HMMA, fp32 accumulate.
//   Calibrated error model: dropping x@Wl cost 2.09e-4 (measured R9);
//   dropping xl@Wh adds an independent equal term -> predicted ~3.0e-4,
//   3.3x margin to the 1e-3 threshold.
// Halves MMAs (16/chunk), A smem, A convert, A LDSM vs R9.

#define D_DIM 256
#define BM 128
#define BN 64
#define BK 32
#define N_CHUNKS (D_DIM / BK)      // 8
#define ROWB 80                    // smem row stride: (32+8) fp16 -> conflict-free ldsm

#define OFF_AH 0
#define OFF_BH (OFF_AH + BM * ROWB)      // 10240
#define STAGE_BYTES (OFF_BH + BN * ROWB) // 15360
#define SMEM_TOTAL (2 * STAGE_BYTES)     // 30720

__device__ __forceinline__ uint32_t smem_u32(const void* p) {
    uint32_t a;
    asm("{ .reg .u64 t; cvta.to.shared.u64 t, %1; cvt.u32.u64 %0, t; }" : "=r"(a) : "l"(p));
    return a;
}

__device__ __forceinline__ void ldsm_x4(uint32_t* r, uint32_t addr) {
    asm volatile("ldmatrix.sync.aligned.m8n8.x4.shared.b16 {%0,%1,%2,%3}, [%4];"
                 : "=r"(r[0]), "=r"(r[1]), "=r"(r[2]), "=r"(r[3]) : "r"(addr));
}

__device__ __forceinline__ void mma_f16(float* d, const uint32_t* a, const uint32_t* b) {
    asm volatile("mma.sync.aligned.m16n8k16.row.col.f32.f16.f16.f32 "
                 "{%0,%1,%2,%3}, {%4,%5,%6,%7}, {%8,%9}, {%0,%1,%2,%3};"
                 : "+f"(d[0]), "+f"(d[1]), "+f"(d[2]), "+f"(d[3])
                 : "r"(a[0]), "r"(a[1]), "r"(a[2]), "r"(a[3]),
                   "r"(b[0]), "r"(b[1]));
}

// float4 -> fp16x4, one 8 B store.
__device__ __forceinline__ void cvt_store(uint32_t addr, float4 v) {
    __half2 h0 = __floats2half2_rn(v.x, v.y);
    __half2 h1 = __floats2half2_rn(v.z, v.w);
    uint32_t h0u = *(uint32_t*)&h0, h1u = *(uint32_t*)&h1;
    asm volatile("st.shared.v2.b32 [%0], {%1, %2};" :: "r"(addr), "r"(h0u), "r"(h1u) : "memory");
}

__global__ __launch_bounds__(256, 2)
void fcgat_hmma(const float* __restrict__ A,     // x  [32768, 256]
                const float* __restrict__ W,     // W  [256, 256]
                const float* __restrict__ bias,  // [256]
                float* __restrict__ C)           // [32768, 256]
{
    extern __shared__ __align__(16) unsigned char smem[];
    const uint32_t sb = smem_u32(smem);

    const int t   = threadIdx.x;
    const int l   = t & 31;
    const int wid = t >> 5;
    const int wm  = wid & 3;          // 4 warps along M
    const int wn  = wid >> 2;         // 2 warps along N
    const int m0  = wm * 32;
    const int n0  = wn * 32;

    const float* Ag = A + (size_t)blockIdx.y * BM * D_DIM;
    const float* Bg = W + (size_t)blockIdx.x * BN * D_DIM;

    float acc[2][4][4];
    #pragma unroll
    for (int i = 0; i < 2; i++)
        #pragma unroll
        for (int j = 0; j < 4; j++)
            #pragma unroll
            for (int c = 0; c < 4; c++)
                acc[i][j][c] = 0.0f;

    const uint32_t a_lane = (uint32_t)((m0 + (l & 15)) * ROWB + (l >> 4) * 16);
    const uint32_t b_lane = (uint32_t)((n0 + (l & 7) + ((l >> 4) << 3)) * ROWB
                                       + ((l >> 3) & 1) * 16);

    float4 pa[4];
    float4 pb[2];

    // ---- prologue: load + store chunk 0 ----
    #pragma unroll
    for (int i = 0; i < 4; i++) {
        int idx = t + i * 256;
        pa[i] = *(const float4*)(Ag + (size_t)(idx >> 3) * D_DIM + (idx & 7) * 4);
    }
    #pragma unroll
    for (int i = 0; i < 2; i++) {
        int idx = t + i * 256;
        pb[i] = *(const float4*)(Bg + (size_t)(idx >> 3) * D_DIM + (idx & 7) * 4);
    }
    #pragma unroll
    for (int i = 0; i < 4; i++) {
        int idx = t + i * 256;
        uint32_t so = (uint32_t)((idx >> 3) * ROWB + (idx & 7) * 8);
        cvt_store(sb + OFF_AH + so, pa[i]);
    }
    #pragma unroll
    for (int i = 0; i < 2; i++) {
        int idx = t + i * 256;
        uint32_t so = (uint32_t)((idx >> 3) * ROWB + (idx & 7) * 8);
        cvt_store(sb + OFF_BH + so, pb[i]);
    }
    __syncthreads();

    uint32_t stage = 0;
    for (int ch = 0; ch < N_CHUNKS; ch++) {
        const bool more = (ch + 1 < N_CHUNKS);
        const int kn = (ch + 1) * BK;

        // (1) issue next chunk's global loads (latency hidden behind MMAs)
        if (more) {
            #pragma unroll
            for (int i = 0; i < 4; i++) {
                int idx = t + i * 256;
                pa[i] = *(const float4*)(Ag + (size_t)(idx >> 3) * D_DIM + kn + (idx & 7) * 4);
            }
            #pragma unroll
            for (int i = 0; i < 2; i++) {
                int idx = t + i * 256;
                pb[i] = *(const float4*)(Bg + (size_t)(idx >> 3) * D_DIM + kn + (idx & 7) * 4);
            }
        }

        // (2) compute current chunk from stage `stage`
        const uint32_t base = sb + stage;
        #pragma unroll
        for (int ks = 0; ks < 2; ks++) {
            const uint32_t ko = (uint32_t)(ks * 32);   // 16 fp16 = 32 B
            uint32_t ah[2][4], bh[2][4];
            #pragma unroll
            for (int i = 0; i < 2; i++)
                ldsm_x4(ah[i], base + OFF_AH + a_lane + ko + i * 16 * ROWB);
            #pragma unroll
            for (int jp = 0; jp < 2; jp++)
                ldsm_x4(bh[jp], base + OFF_BH + b_lane + ko + jp * 16 * ROWB);

            #pragma unroll
            for (int i = 0; i < 2; i++)
                #pragma unroll
                for (int j = 0; j < 4; j++) {
                    const uint32_t* bhf = bh[j >> 1] + (j & 1) * 2;
                    mma_f16(acc[i][j], ah[i], bhf);
                }
        }

        // (3) convert + store next chunk into the other stage
        const uint32_t nbase = sb + (stage ^ STAGE_BYTES);
        if (more) {
            #pragma unroll
            for (int i = 0; i < 4; i++) {
                int idx = t + i * 256;
                uint32_t so = (uint32_t)((idx >> 3) * ROWB + (idx & 7) * 8);
                cvt_store(nbase + OFF_AH + so, pa[i]);
            }
            #pragma unroll
            for (int i = 0; i < 2; i++) {
                int idx = t + i * 256;
                uint32_t so = (uint32_t)((idx >> 3) * ROWB + (idx & 7) * 8);
                cvt_store(nbase + OFF_BH + so, pb[i]);
            }
        }

        // (4) single barrier per chunk
        __syncthreads();
        stage ^= STAGE_BYTES;
    }

    // ---- epilogue: bias + relu ----
    const int g  = l >> 2;
    const int tc = l & 3;
    #pragma unroll
    for (int i = 0; i < 2; i++) {
        const size_t r0 = (size_t)blockIdx.y * BM + m0 + 16 * i + g;
        const size_t r1 = r0 + 8;
        #pragma unroll
        for (int j = 0; j < 4; j++) {
            const int col = blockIdx.x * BN + n0 + 8 * j + 2 * tc;
            float2 bv = *(const float2*)(bias + col);
            float2 o0, o1;
            o0.x = fmaxf(acc[i][j][0] + bv.x, 0.0f);
            o0.y = fmaxf(acc[i][j][1] + bv.y, 0.0f);
            o1.x = fmaxf(acc[i][j][2] + bv.x, 0.0f);
            o1.y = fmaxf(acc[i][j][3] + bv.y, 0.0f);
            *(float2*)(C + r0 * D_DIM + col) = o0;
            *(float2*)(C + r1 * D_DIM + col) = o1;
        }
    }
}

extern "C" void kernel_launch(void* const* d_in, const int* in_sizes, int n_in,
                              void* d_out, int out_size)
{
    const float* x   = (const float*)d_in[0];
    const float* W_w = (const float*)d_in[1];
    const float* W_b = (const float*)d_in[2];
    float* out = (float*)d_out;

    int M = in_sizes[0] / D_DIM;                  // 32768
    cudaFuncSetAttribute(fcgat_hmma,
                         cudaFuncAttributeMaxDynamicSharedMemorySize, SMEM_TOTAL);
    dim3 grid(D_DIM / BN, M / BM);                // (4, 256) = 1024 CTAs
    fcgat_hmma<<<grid, 256, SMEM_TOTAL>>>(x, W_w, W_b, out);
}

// round 11
// speedup vs baseline: 1.8498x; 1.0252x over previous
#include <cuda_runtime.h>
#include <cuda_fp16.h>
#include <cstdint>

// out = relu(x @ W_w^T + W_b)   (attention collapses: softmax rows sum to 1).
//
// R11 = R10 with BK 32 -> 64 (single variable):
//   - MMA chain/warp/chunk 16 -> 32: covers the ~600cyc LDG latency that R10
//     exposed (issue was 15.4%, all pipes idle -> latency-bound diagnosis)
//   - barriers 8 -> 4
//   - prefetch 48 float4-regs (R10 live demand ~87 of its 128; fits, no spill)
// rel_err must stay bit-identical at 2.944e-4 (same k accumulation order).

#define D_DIM 256
#define BM 128
#define BN 64
#define BK 64
#define N_CHUNKS (D_DIM / BK)      // 4
#define ROWB 144                   // (64+8) fp16 row stride: mod 128 = 16 -> conflict-free

#define OFF_A 0
#define OFF_B (BM * ROWB)                 // 18432
#define STAGE_BYTES (OFF_B + BN * ROWB)   // 27648
#define SMEM_TOTAL (2 * STAGE_BYTES)      // 55296

__device__ __forceinline__ uint32_t smem_u32(const void* p) {
    uint32_t a;
    asm("{ .reg .u64 t; cvta.to.shared.u64 t, %1; cvt.u32.u64 %0, t; }" : "=r"(a) : "l"(p));
    return a;
}

__device__ __forceinline__ void ldsm_x4(uint32_t* r, uint32_t addr) {
    asm volatile("ldmatrix.sync.aligned.m8n8.x4.shared.b16 {%0,%1,%2,%3}, [%4];"
                 : "=r"(r[0]), "=r"(r[1]), "=r"(r[2]), "=r"(r[3]) : "r"(addr));
}

__device__ __forceinline__ void mma_f16(float* d, const uint32_t* a, const uint32_t* b) {
    asm volatile("mma.sync.aligned.m16n8k16.row.col.f32.f16.f16.f32 "
                 "{%0,%1,%2,%3}, {%4,%5,%6,%7}, {%8,%9}, {%0,%1,%2,%3};"
                 : "+f"(d[0]), "+f"(d[1]), "+f"(d[2]), "+f"(d[3])
                 : "r"(a[0]), "r"(a[1]), "r"(a[2]), "r"(a[3]),
                   "r"(b[0]), "r"(b[1]));
}

// float4 -> fp16x4, one 8 B store.
__device__ __forceinline__ void cvt_store(uint32_t addr, float4 v) {
    __half2 h0 = __floats2half2_rn(v.x, v.y);
    __half2 h1 = __floats2half2_rn(v.z, v.w);
    uint32_t h0u = *(uint32_t*)&h0, h1u = *(uint32_t*)&h1;
    asm volatile("st.shared.v2.b32 [%0], {%1, %2};" :: "r"(addr), "r"(h0u), "r"(h1u) : "memory");
}

__global__ __launch_bounds__(256, 2)
void fcgat_hmma(const float* __restrict__ A,     // x  [32768, 256]
                const float* __restrict__ W,     // W  [256, 256]
                const float* __restrict__ bias,  // [256]
                float* __restrict__ C)           // [32768, 256]
{
    extern __shared__ __align__(16) unsigned char smem[];
    const uint32_t sb = smem_u32(smem);

    const int t   = threadIdx.x;
    const int l   = t & 31;
    const int wid = t >> 5;
    const int wm  = wid & 3;          // 4 warps along M
    const int wn  = wid >> 2;         // 2 warps along N
    const int m0  = wm * 32;
    const int n0  = wn * 32;

    const float* Ag = A + (size_t)blockIdx.y * BM * D_DIM;
    const float* Bg = W + (size_t)blockIdx.x * BN * D_DIM;

    float acc[2][4][4];
    #pragma unroll
    for (int i = 0; i < 2; i++)
        #pragma unroll
        for (int j = 0; j < 4; j++)
            #pragma unroll
            for (int c = 0; c < 4; c++)
                acc[i][j][c] = 0.0f;

    const uint32_t a_lane = (uint32_t)((m0 + (l & 15)) * ROWB + (l >> 4) * 16);
    const uint32_t b_lane = (uint32_t)((n0 + (l & 7) + ((l >> 4) << 3)) * ROWB
                                       + ((l >> 3) & 1) * 16);

    // Per-chunk loads: A 128 rows x 16 float4 = 2048 -> 8/thread
    //                  B  64 rows x 16 float4 = 1024 -> 4/thread
    float4 pa[8];
    float4 pb[4];

    // ---- prologue: load + convert + store chunk 0 ----
    #pragma unroll
    for (int i = 0; i < 8; i++) {
        int idx = t + i * 256;
        pa[i] = *(const float4*)(Ag + (size_t)(idx >> 4) * D_DIM + (idx & 15) * 4);
    }
    #pragma unroll
    for (int i = 0; i < 4; i++) {
        int idx = t + i * 256;
        pb[i] = *(const float4*)(Bg + (size_t)(idx >> 4) * D_DIM + (idx & 15) * 4);
    }
    #pragma unroll
    for (int i = 0; i < 8; i++) {
        int idx = t + i * 256;
        cvt_store(sb + OFF_A + (uint32_t)((idx >> 4) * ROWB + (idx & 15) * 8), pa[i]);
    }
    #pragma unroll
    for (int i = 0; i < 4; i++) {
        int idx = t + i * 256;
        cvt_store(sb + OFF_B + (uint32_t)((idx >> 4) * ROWB + (idx & 15) * 8), pb[i]);
    }
    __syncthreads();

    uint32_t stage = 0;
    for (int ch = 0; ch < N_CHUNKS; ch++) {
        const bool more = (ch + 1 < N_CHUNKS);
        const int kn = (ch + 1) * BK;

        // (1) issue next chunk's global loads (latency hidden behind 32 MMAs)
        if (more) {
            #pragma unroll
            for (int i = 0; i < 8; i++) {
                int idx = t + i * 256;
                pa[i] = *(const float4*)(Ag + (size_t)(idx >> 4) * D_DIM + kn + (idx & 15) * 4);
            }
            #pragma unroll
            for (int i = 0; i < 4; i++) {
                int idx = t + i * 256;
                pb[i] = *(const float4*)(Bg + (size_t)(idx >> 4) * D_DIM + kn + (idx & 15) * 4);
            }
        }

        // (2) compute current chunk: 4 k16 steps, 8 MMAs each
        const uint32_t base = sb + stage;
        #pragma unroll
        for (int ks = 0; ks < 4; ks++) {
            const uint32_t ko = (uint32_t)(ks * 32);   // 16 fp16 = 32 B
            uint32_t ah[2][4], bh[2][4];
            #pragma unroll
            for (int i = 0; i < 2; i++)
                ldsm_x4(ah[i], base + OFF_A + a_lane + ko + i * 16 * ROWB);
            #pragma unroll
            for (int jp = 0; jp < 2; jp++)
                ldsm_x4(bh[jp], base + OFF_B + b_lane + ko + jp * 16 * ROWB);

            #pragma unroll
            for (int i = 0; i < 2; i++)
                #pragma unroll
                for (int j = 0; j < 4; j++) {
                    const uint32_t* bhf = bh[j >> 1] + (j & 1) * 2;
                    mma_f16(acc[i][j], ah[i], bhf);
                }
        }

        // (3) convert + store next chunk into the other stage
        if (more) {
            const uint32_t nbase = sb + (stage ^ STAGE_BYTES);
            #pragma unroll
            for (int i = 0; i < 8; i++) {
                int idx = t + i * 256;
                cvt_store(nbase + OFF_A + (uint32_t)((idx >> 4) * ROWB + (idx & 15) * 8), pa[i]);
            }
            #pragma unroll
            for (int i = 0; i < 4; i++) {
                int idx = t + i * 256;
                cvt_store(nbase + OFF_B + (uint32_t)((idx >> 4) * ROWB + (idx & 15) * 8), pb[i]);
            }
        }

        // (4) single barrier per chunk
        __syncthreads();
        stage ^= STAGE_BYTES;
    }

    // ---- epilogue: bias + relu ----
    const int g  = l >> 2;
    const int tc = l & 3;
    #pragma unroll
    for (int i = 0; i < 2; i++) {
        const size_t r0 = (size_t)blockIdx.y * BM + m0 + 16 * i + g;
        const size_t r1 = r0 + 8;
        #pragma unroll
        for (int j = 0; j < 4; j++) {
            const int col = blockIdx.x * BN + n0 + 8 * j + 2 * tc;
            float2 bv = *(const float2*)(bias + col);
            float2 o0, o1;
            o0.x = fmaxf(acc[i][j][0] + bv.x, 0.0f);
            o0.y = fmaxf(acc[i][j][1] + bv.y, 0.0f);
            o1.x = fmaxf(acc[i][j][2] + bv.x, 0.0f);
            o1.y = fmaxf(acc[i][j][3] + bv.y, 0.0f);
            *(float2*)(C + r0 * D_DIM + col) = o0;
            *(float2*)(C + r1 * D_DIM + col) = o1;
        }
    }
}

extern "C" void kernel_launch(void* const* d_in, const int* in_sizes, int n_in,
                              void* d_out, int out_size)
{
    const float* x   = (const float*)d_in[0];
    const float* W_w = (const float*)d_in[1];
    const float* W_b = (const float*)d_in[2];
    float* out = (float*)d_out;

    int M = in_sizes[0] / D_DIM;                  // 32768
    cudaFuncSetAttribute(fcgat_hmma,
                         cudaFuncAttributeMaxDynamicSharedMemorySize, SMEM_TOTAL);
    dim3 grid(D_DIM / BN, M / BM);                // (4, 256) = 1024 CTAs
    fcgat_hmma<<<grid, 256, SMEM_TOTAL>>>(x, W_w, W_b, out);
}